// round 3
// baseline (speedup 1.0000x reference)
#include <cuda_runtime.h>
#include <cstdint>
#include <math.h>

#define NROWS   100000
#define NFEAT   512
#define NHID    256
#define NCLASS  41

// ---------------- scratch (device globals; 16B-aligned for float4) ---------
__device__ float4 g_buf1_v[(size_t)NROWS * NHID / 4];   // XW1, then A@h
__device__ float4 g_buf2_v[(size_t)NROWS * NHID / 4];   // h = relu(A(XW1)+b1)
__device__ int    g_rowptr[NROWS + 1];

// ---------------- row_ptr: lower_bound of i in sorted rows -----------------
__global__ void build_rowptr(const int* __restrict__ rows, int nnz) {
    int i = blockIdx.x * blockDim.x + threadIdx.x;
    if (i > NROWS) return;
    int lo = 0, hi = nnz;
    while (lo < hi) {
        int mid = (lo + hi) >> 1;
        if (rows[mid] < i) lo = mid + 1; else hi = mid;
    }
    g_rowptr[i] = lo;
}

// ---------------- SGEMM1: C[M,256] = A[M,512] @ B[512,256] ------------------
// Block tile 128x64, K-tile 32, 256 threads, 8x4 microtile per thread.
__global__ __launch_bounds__(256) void sgemm1(const float* __restrict__ A,
                                              const float* __restrict__ B,
                                              float* __restrict__ C) {
    __shared__ __align__(16) float sA[128][32];
    __shared__ __align__(16) float sB[32][64];

    const int tid = threadIdx.x;
    const int tx = tid & 15;          // 0..15  -> 4 cols each
    const int ty = tid >> 4;          // 0..15  -> 8 rows each
    const int row0 = blockIdx.x * 128;
    const int col0 = blockIdx.y * 64;

    const int ar = tid >> 1;          // 0..127
    const int ac = (tid & 1) * 16;    // 0 or 16
    const int br = tid >> 3;          // 0..31
    const int bc = (tid & 7) * 8;     // 0..56

    const bool aval = (row0 + ar) < NROWS;

    float acc[8][4];
#pragma unroll
    for (int i = 0; i < 8; i++)
#pragma unroll
        for (int j = 0; j < 4; j++) acc[i][j] = 0.f;

    for (int k0 = 0; k0 < NFEAT; k0 += 32) {
        if (aval) {
            const float4* ap = (const float4*)(A + (size_t)(row0 + ar) * NFEAT + k0 + ac);
#pragma unroll
            for (int q = 0; q < 4; q++)
                *(float4*)&sA[ar][ac + q * 4] = ap[q];
        } else {
            float4 z = {0.f, 0.f, 0.f, 0.f};
#pragma unroll
            for (int q = 0; q < 4; q++)
                *(float4*)&sA[ar][ac + q * 4] = z;
        }
        {
            const float4* bp = (const float4*)(B + (size_t)(k0 + br) * NHID + col0 + bc);
            *(float4*)&sB[br][bc]     = bp[0];
            *(float4*)&sB[br][bc + 4] = bp[1];
        }
        __syncthreads();

#pragma unroll
        for (int kk = 0; kk < 32; kk++) {
            float4 bv = *(const float4*)&sB[kk][tx * 4];
            float a[8];
#pragma unroll
            for (int i = 0; i < 8; i++) a[i] = sA[ty * 8 + i][kk];
#pragma unroll
            for (int i = 0; i < 8; i++) {
                acc[i][0] += a[i] * bv.x;
                acc[i][1] += a[i] * bv.y;
                acc[i][2] += a[i] * bv.z;
                acc[i][3] += a[i] * bv.w;
            }
        }
        __syncthreads();
    }

#pragma unroll
    for (int i = 0; i < 8; i++) {
        int row = row0 + ty * 8 + i;
        if (row < NROWS) {
            float4 v = {acc[i][0], acc[i][1], acc[i][2], acc[i][3]};
            *(float4*)(C + (size_t)row * NHID + col0 + tx * 4) = v;
        }
    }
}

// ---------------- SpMM (CSR, warp per row), optional bias+relu -------------
__global__ __launch_bounds__(256) void spmm_k(const int* __restrict__ cols,
                                              const float* __restrict__ vals,
                                              const float4* __restrict__ dense,
                                              const float* __restrict__ bias,
                                              float4* __restrict__ out,
                                              int do_relu) {
    int row  = blockIdx.x * (blockDim.x >> 5) + (threadIdx.x >> 5);
    if (row >= NROWS) return;
    int lane = threadIdx.x & 31;

    int s = g_rowptr[row];
    int e = g_rowptr[row + 1];

    float4 acc0 = {0.f, 0.f, 0.f, 0.f};
    float4 acc1 = {0.f, 0.f, 0.f, 0.f};

    for (int j = s; j < e; j++) {
        int   c = __ldg(cols + j);
        float v = __ldg(vals + j);
        const float4* p = dense + (size_t)c * (NHID / 4);
        float4 d0 = __ldg(p + lane);
        float4 d1 = __ldg(p + lane + 32);
        acc0.x += v * d0.x; acc0.y += v * d0.y; acc0.z += v * d0.z; acc0.w += v * d0.w;
        acc1.x += v * d1.x; acc1.y += v * d1.y; acc1.z += v * d1.z; acc1.w += v * d1.w;
    }

    if (bias) {
        // scalar loads: bias alignment never an issue
        int c0 = lane * 4, c1 = lane * 4 + 128;
        acc0.x += __ldg(bias + c0);     acc0.y += __ldg(bias + c0 + 1);
        acc0.z += __ldg(bias + c0 + 2); acc0.w += __ldg(bias + c0 + 3);
        acc1.x += __ldg(bias + c1);     acc1.y += __ldg(bias + c1 + 1);
        acc1.z += __ldg(bias + c1 + 2); acc1.w += __ldg(bias + c1 + 3);
    }
    if (do_relu) {
        acc0.x = fmaxf(acc0.x, 0.f); acc0.y = fmaxf(acc0.y, 0.f);
        acc0.z = fmaxf(acc0.z, 0.f); acc0.w = fmaxf(acc0.w, 0.f);
        acc1.x = fmaxf(acc1.x, 0.f); acc1.y = fmaxf(acc1.y, 0.f);
        acc1.z = fmaxf(acc1.z, 0.f); acc1.w = fmaxf(acc1.w, 0.f);
    }

    float4* o = out + (size_t)row * (NHID / 4);
    o[lane]      = acc0;
    o[lane + 32] = acc1;
}

// ---------------- GEMM2 (256->41) + bias + log_softmax, fused --------------
__global__ __launch_bounds__(256) void gemm2_lsm(const float4* __restrict__ ah,
                                                 const float* __restrict__ w2,
                                                 const float* __restrict__ b2,
                                                 float* __restrict__ out) {
    __shared__ __align__(16) float sw[NHID * NCLASS];   // 41984 B
    __shared__ __align__(16) float srow[4][NHID];
    __shared__ __align__(16) float slog[4][NCLASS];
    __shared__ __align__(16) float sb[NCLASS];

    const int tid = threadIdx.x;
    for (int i = tid; i < NHID * NCLASS; i += 256) sw[i] = w2[i];
    if (tid < NCLASS) sb[tid] = b2[tid];
    __syncthreads();

    const int group = tid >> 6;   // 0..3
    const int gt    = tid & 63;   // 0..63

    for (int row0 = blockIdx.x * 4; row0 < NROWS; row0 += gridDim.x * 4) {
        const int row = row0 + group;
        const bool rok = row < NROWS;

        if (rok) {
            float4 v = ah[(size_t)row * (NHID / 4) + gt];
            ((float4*)srow[group])[gt] = v;
        }
        __syncthreads();

        if (rok && gt < NCLASS) {
            float a = sb[gt];
#pragma unroll 8
            for (int k = 0; k < NHID; k++)
                a += srow[group][k] * sw[k * NCLASS + gt];
            slog[group][gt] = a;
        }
        __syncthreads();

        if (rok && gt < NCLASS) {
            float m = -INFINITY;
#pragma unroll
            for (int k = 0; k < NCLASS; k++) m = fmaxf(m, slog[group][k]);
            float ssum = 0.f;
#pragma unroll
            for (int k = 0; k < NCLASS; k++) ssum += expf(slog[group][k] - m);
            out[(size_t)row * NCLASS + gt] = slog[group][gt] - m - logf(ssum);
        }
        __syncthreads();
    }
}

// ---------------------------------------------------------------------------
extern "C" void kernel_launch(void* const* d_in, const int* in_sizes, int n_in,
                              void* d_out, int out_size) {
    const float* x        = (const float*)d_in[0];
    const int*   adj_rows = (const int*)  d_in[1];
    const int*   adj_cols = (const int*)  d_in[2];
    const float* adj_vals = (const float*)d_in[3];
    const float* w1       = (const float*)d_in[4];
    const float* b1       = (const float*)d_in[5];
    const float* w2       = (const float*)d_in[6];
    const float* b2       = (const float*)d_in[7];
    float* out = (float*)d_out;
    const int nnz = in_sizes[1];

    float4* buf1; cudaGetSymbolAddress((void**)&buf1, g_buf1_v);
    float4* buf2; cudaGetSymbolAddress((void**)&buf2, g_buf2_v);

    // 1) CSR row pointers from sorted rows
    build_rowptr<<<(NROWS + 1 + 255) / 256, 256>>>(adj_rows, nnz);

    // 2) XW1 -> buf1
    dim3 g1((NROWS + 127) / 128, NHID / 64);
    sgemm1<<<g1, 256>>>(x, w1, (float*)buf1);

    // 3) h = relu(A @ buf1 + b1) -> buf2
    int spmm_blocks = (NROWS * 32 + 255) / 256;
    spmm_k<<<spmm_blocks, 256>>>(adj_cols, adj_vals, buf1, b1, buf2, 1);

    // 4) A @ h -> buf1
    spmm_k<<<spmm_blocks, 256>>>(adj_cols, adj_vals, buf2, nullptr, buf1, 0);

    // 5) log_softmax(buf1 @ W2 + b2) -> out
    gemm2_lsm<<<2048, 256>>>(buf1, w2, b2, out);
}

// round 4
// speedup vs baseline: 1.1213x; 1.1213x over previous
#include <cuda_runtime.h>
#include <cstdint>
#include <math.h>

#define NROWS   100000
#define NFEAT   512
#define NHID    256
#define NCLASS  41

// ---------------- scratch (device globals) ----------------------------------
__device__ float4 g_buf1_v[(size_t)NROWS * NHID / 4];   // XW1, then A@h
__device__ float4 g_buf2_v[(size_t)NROWS * NHID / 4];   // h = relu(A(XW1)+b1)
__device__ int    g_rowptr[NROWS + 1];

// ---------------- row_ptr: lower_bound of i in sorted rows ------------------
__global__ void build_rowptr(const int* __restrict__ rows, int nnz) {
    int i = blockIdx.x * blockDim.x + threadIdx.x;
    if (i > NROWS) return;
    int lo = 0, hi = nnz;
    while (lo < hi) {
        int mid = (lo + hi) >> 1;
        if (rows[mid] < i) lo = mid + 1; else hi = mid;
    }
    g_rowptr[i] = lo;
}

// ---------------- tf32 helpers ----------------------------------------------
__device__ __forceinline__ uint32_t f2tf32(float a) {
    uint32_t r;
    asm("cvt.rna.tf32.f32 %0, %1;" : "=r"(r) : "f"(a));
    return r;
}
__device__ __forceinline__ void split_tf32(float a, uint32_t& hi, uint32_t& lo) {
    hi = f2tf32(a);
    float hf = __uint_as_float(hi);
    lo = f2tf32(a - hf);
}
__device__ __forceinline__ void mma_tf32(float* c, const uint32_t* a, const uint32_t* b) {
    asm volatile(
        "mma.sync.aligned.m16n8k8.row.col.f32.tf32.tf32.f32 "
        "{%0,%1,%2,%3}, {%4,%5,%6,%7}, {%8,%9}, {%0,%1,%2,%3};"
        : "+f"(c[0]), "+f"(c[1]), "+f"(c[2]), "+f"(c[3])
        : "r"(a[0]), "r"(a[1]), "r"(a[2]), "r"(a[3]),
          "r"(b[0]), "r"(b[1]));
}

// ---------------- SGEMM1 via 3xTF32 tensor MMA -------------------------------
// C[M,256] = A[M,512] @ B[512,256].  Block tile 128x128, BK=16, 256 threads,
// 8 warps as 2(m) x 4(n); each warp computes 64x32 via 4x4 m16n8k8 tiles.
#define BM 128
#define BN 128
#define BK 16
#define SAP 20      // sA row pad (floats): conflict-free a-frag reads
#define SBP 132     // sB row pad (floats)

__global__ __launch_bounds__(256) void sgemm_tf32(const float* __restrict__ A,
                                                  const float* __restrict__ B,
                                                  float* __restrict__ C) {
    __shared__ __align__(16) float sA[BM][SAP];
    __shared__ __align__(16) float sB[BK][SBP];

    const int tid  = threadIdx.x;
    const int lane = tid & 31;
    const int warp = tid >> 5;
    const int warp_m = warp & 1;     // 0..1 -> 64 rows each
    const int warp_n = warp >> 1;    // 0..3 -> 32 cols each
    const int row0 = blockIdx.x * BM;
    const int col0 = blockIdx.y * BN;

    const int tr = lane >> 2;        // 0..7
    const int tc = lane & 3;         // 0..3

    float acc[4][4][4];
#pragma unroll
    for (int i = 0; i < 4; i++)
#pragma unroll
        for (int j = 0; j < 4; j++)
#pragma unroll
            for (int q = 0; q < 4; q++) acc[i][j][q] = 0.f;

    for (int k0 = 0; k0 < NFEAT; k0 += BK) {
        // ---- load A tile (128x16) : 512 float4, 2 per thread ----
#pragma unroll
        for (int q = 0; q < 2; q++) {
            int idx = tid * 2 + q;
            int r = idx >> 2, c4 = (idx & 3) * 4;
            float4 v = {0.f, 0.f, 0.f, 0.f};
            if (row0 + r < NROWS)
                v = *(const float4*)(A + (size_t)(row0 + r) * NFEAT + k0 + c4);
            *(float4*)&sA[r][c4] = v;
        }
        // ---- load B tile (16x128) : 512 float4, 2 per thread ----
#pragma unroll
        for (int q = 0; q < 2; q++) {
            int idx = tid * 2 + q;
            int r = idx >> 5, c4 = (idx & 31) * 4;
            float4 v = *(const float4*)(B + (size_t)(k0 + r) * NHID + col0 + c4);
            *(float4*)&sB[r][c4] = v;
        }
        __syncthreads();

#pragma unroll
        for (int kk = 0; kk < BK; kk += 8) {
            // B fragments for the 4 n-tiles of this warp
            uint32_t bh[4][2], bl[4][2];
#pragma unroll
            for (int wn = 0; wn < 4; wn++) {
                int n = warp_n * 32 + wn * 8 + tr;
                float b0 = sB[kk + tc][n];
                float b1 = sB[kk + tc + 4][n];
                split_tf32(b0, bh[wn][0], bl[wn][0]);
                split_tf32(b1, bh[wn][1], bl[wn][1]);
            }
#pragma unroll
            for (int wm = 0; wm < 4; wm++) {
                int m = warp_m * 64 + wm * 16 + tr;
                float a0 = sA[m][kk + tc];
                float a1 = sA[m + 8][kk + tc];
                float a2 = sA[m][kk + tc + 4];
                float a3 = sA[m + 8][kk + tc + 4];
                uint32_t ah[4], al[4];
                split_tf32(a0, ah[0], al[0]);
                split_tf32(a1, ah[1], al[1]);
                split_tf32(a2, ah[2], al[2]);
                split_tf32(a3, ah[3], al[3]);
#pragma unroll
                for (int wn = 0; wn < 4; wn++) {
                    mma_tf32(acc[wm][wn], ah, bh[wn]);  // hi*hi
                    mma_tf32(acc[wm][wn], ah, bl[wn]);  // hi*lo
                    mma_tf32(acc[wm][wn], al, bh[wn]);  // lo*hi
                }
            }
        }
        __syncthreads();
    }

    // ---- epilogue: each tile writes 2 rows x (2-float pairs) per thread ----
#pragma unroll
    for (int wm = 0; wm < 4; wm++) {
        int r = row0 + warp_m * 64 + wm * 16 + tr;
#pragma unroll
        for (int wn = 0; wn < 4; wn++) {
            int c = col0 + warp_n * 32 + wn * 8 + tc * 2;
            if (r < NROWS) {
                float2 v = {acc[wm][wn][0], acc[wm][wn][1]};
                *(float2*)(C + (size_t)r * NHID + c) = v;
            }
            if (r + 8 < NROWS) {
                float2 v = {acc[wm][wn][2], acc[wm][wn][3]};
                *(float2*)(C + (size_t)(r + 8) * NHID + c) = v;
            }
        }
    }
}

// ---------------- SpMM (CSR, warp per row), optional bias+relu --------------
__global__ __launch_bounds__(256) void spmm_k(const int* __restrict__ cols,
                                              const float* __restrict__ vals,
                                              const float4* __restrict__ dense,
                                              const float* __restrict__ bias,
                                              float4* __restrict__ out,
                                              int do_relu) {
    int row  = blockIdx.x * (blockDim.x >> 5) + (threadIdx.x >> 5);
    if (row >= NROWS) return;
    int lane = threadIdx.x & 31;

    int s = g_rowptr[row];
    int e = g_rowptr[row + 1];

    float4 acc0 = {0.f, 0.f, 0.f, 0.f};
    float4 acc1 = {0.f, 0.f, 0.f, 0.f};

    for (int j = s; j < e; j++) {
        int   c = __ldg(cols + j);
        float v = __ldg(vals + j);
        const float4* p = dense + (size_t)c * (NHID / 4);
        float4 d0 = __ldg(p + lane);
        float4 d1 = __ldg(p + lane + 32);
        acc0.x += v * d0.x; acc0.y += v * d0.y; acc0.z += v * d0.z; acc0.w += v * d0.w;
        acc1.x += v * d1.x; acc1.y += v * d1.y; acc1.z += v * d1.z; acc1.w += v * d1.w;
    }

    if (bias) {
        int c0 = lane * 4, c1 = lane * 4 + 128;
        acc0.x += __ldg(bias + c0);     acc0.y += __ldg(bias + c0 + 1);
        acc0.z += __ldg(bias + c0 + 2); acc0.w += __ldg(bias + c0 + 3);
        acc1.x += __ldg(bias + c1);     acc1.y += __ldg(bias + c1 + 1);
        acc1.z += __ldg(bias + c1 + 2); acc1.w += __ldg(bias + c1 + 3);
    }
    if (do_relu) {
        acc0.x = fmaxf(acc0.x, 0.f); acc0.y = fmaxf(acc0.y, 0.f);
        acc0.z = fmaxf(acc0.z, 0.f); acc0.w = fmaxf(acc0.w, 0.f);
        acc1.x = fmaxf(acc1.x, 0.f); acc1.y = fmaxf(acc1.y, 0.f);
        acc1.z = fmaxf(acc1.z, 0.f); acc1.w = fmaxf(acc1.w, 0.f);
    }

    float4* o = out + (size_t)row * (NHID / 4);
    o[lane]      = acc0;
    o[lane + 32] = acc1;
}

// ---------------- GEMM2 (256->41) + bias + log_softmax, fused ---------------
__global__ __launch_bounds__(256) void gemm2_lsm(const float4* __restrict__ ah,
                                                 const float* __restrict__ w2,
                                                 const float* __restrict__ b2,
                                                 float* __restrict__ out) {
    __shared__ __align__(16) float sw[NHID * NCLASS];   // 41984 B
    __shared__ __align__(16) float srow[4][NHID];
    __shared__ __align__(16) float slog[4][NCLASS];
    __shared__ __align__(16) float sb[NCLASS];

    const int tid = threadIdx.x;
    for (int i = tid; i < NHID * NCLASS; i += 256) sw[i] = w2[i];
    if (tid < NCLASS) sb[tid] = b2[tid];
    __syncthreads();

    const int group = tid >> 6;   // 0..3
    const int gt    = tid & 63;   // 0..63

    for (int row0 = blockIdx.x * 4; row0 < NROWS; row0 += gridDim.x * 4) {
        const int row = row0 + group;
        const bool rok = row < NROWS;

        if (rok) {
            float4 v = ah[(size_t)row * (NHID / 4) + gt];
            ((float4*)srow[group])[gt] = v;
        }
        __syncthreads();

        if (rok && gt < NCLASS) {
            float a = sb[gt];
#pragma unroll 8
            for (int k = 0; k < NHID; k++)
                a += srow[group][k] * sw[k * NCLASS + gt];
            slog[group][gt] = a;
        }
        __syncthreads();

        if (rok && gt < NCLASS) {
            float m = -INFINITY;
#pragma unroll
            for (int k = 0; k < NCLASS; k++) m = fmaxf(m, slog[group][k]);
            float ssum = 0.f;
#pragma unroll
            for (int k = 0; k < NCLASS; k++) ssum += expf(slog[group][k] - m);
            out[(size_t)row * NCLASS + gt] = slog[group][gt] - m - logf(ssum);
        }
        __syncthreads();
    }
}

// -----------------------------------------------------------------------------
extern "C" void kernel_launch(void* const* d_in, const int* in_sizes, int n_in,
                              void* d_out, int out_size) {
    const float* x        = (const float*)d_in[0];
    const int*   adj_rows = (const int*)  d_in[1];
    const int*   adj_cols = (const int*)  d_in[2];
    const float* adj_vals = (const float*)d_in[3];
    const float* w1       = (const float*)d_in[4];
    const float* b1       = (const float*)d_in[5];
    const float* w2       = (const float*)d_in[6];
    const float* b2       = (const float*)d_in[7];
    float* out = (float*)d_out;
    const int nnz = in_sizes[1];

    float4* buf1; cudaGetSymbolAddress((void**)&buf1, g_buf1_v);
    float4* buf2; cudaGetSymbolAddress((void**)&buf2, g_buf2_v);

    // 1) CSR row pointers from sorted rows
    build_rowptr<<<(NROWS + 1 + 255) / 256, 256>>>(adj_rows, nnz);

    // 2) XW1 -> buf1 (3xTF32 tensor GEMM)
    dim3 g1((NROWS + BM - 1) / BM, NHID / BN);
    sgemm_tf32<<<g1, 256>>>(x, w1, (float*)buf1);

    // 3) h = relu(A @ buf1 + b1) -> buf2
    int spmm_blocks = (NROWS * 32 + 255) / 256;
    spmm_k<<<spmm_blocks, 256>>>(adj_cols, adj_vals, buf1, b1, buf2, 1);

    // 4) A @ h -> buf1
    spmm_k<<<spmm_blocks, 256>>>(adj_cols, adj_vals, buf2, nullptr, buf1, 0);

    // 5) log_softmax(buf1 @ W2 + b2) -> out
    gemm2_lsm<<<2048, 256>>>(buf1, w2, b2, out);
}